// round 14
// baseline (speedup 1.0000x reference)
#include <cuda_runtime.h>
#include <cuda_fp16.h>
#include <stdint.h>

// Round 13 resubmission — previous bench failed in infra (container failed
// twice), candidate never evaluated.
// GEMM prefetches its 64KB gumbel tile into the two dead smem stages during
// kt=2/3 (cp.async pipeline idle there), removing the gumbel DRAM read from
// the epilogue critical path. Epilogue reads smem with a 64B XOR swizzle.
// iter keeps the R12 f32x2 form (measured at its DRAM floor).

// ---------------------------------------------------------------------------
#define QDIM   4096
#define NDIM   8192
#define DDIM   256
#define BM     128
#define BN     128
#define BK     64
#define NKT    4            // 256/64
#define STAGES 3
#define NITER  10

typedef unsigned long long u64;

// ---------------------------------------------------------------------------
// Device scratch (no allocation allowed)
// ---------------------------------------------------------------------------
__device__ __align__(128) __half g_A[(size_t)QDIM * DDIM];            // 2 MB
__device__ __align__(128) __half g_B[(size_t)NDIM * DDIM];            // 4 MB
__device__ __align__(128) float g_q2[QDIM];
__device__ __align__(128) float g_n2[NDIM];
__device__ __align__(128) float g_w[(size_t)QDIM * NDIM];             // 128 MB (stores e=exp(w))

// ---------------------------------------------------------------------------
// PTX helpers
// ---------------------------------------------------------------------------
__device__ __forceinline__ uint32_t smem_to_u32(const void* p) {
    uint32_t a;
    asm("{ .reg .u64 t; cvta.to.shared.u64 t, %1; cvt.u32.u64 %0, t; }"
        : "=r"(a) : "l"(p));
    return a;
}

__device__ __forceinline__ void cpasync16(uint32_t dst, const void* src) {
    asm volatile("cp.async.cg.shared.global [%0], [%1], 16;"
                 :: "r"(dst), "l"(src) : "memory");
}
__device__ __forceinline__ void cp_commit() {
    asm volatile("cp.async.commit_group;" ::: "memory");
}
template <int N> __device__ __forceinline__ void cp_wait() {
    asm volatile("cp.async.wait_group %0;" :: "n"(N) : "memory");
}

__device__ __forceinline__ void ldmatrix_x4(uint32_t* r, uint32_t addr) {
    asm volatile("ldmatrix.sync.aligned.m8n8.x4.shared.b16 {%0,%1,%2,%3}, [%4];"
                 : "=r"(r[0]), "=r"(r[1]), "=r"(r[2]), "=r"(r[3]) : "r"(addr));
}

__device__ __forceinline__ void mma_fp16(float* c, const uint32_t* a,
                                         const uint32_t* b) {
    asm volatile(
        "mma.sync.aligned.m16n8k16.row.col.f32.f16.f16.f32 "
        "{%0,%1,%2,%3}, {%4,%5,%6,%7}, {%8,%9}, {%0,%1,%2,%3};"
        : "+f"(c[0]), "+f"(c[1]), "+f"(c[2]), "+f"(c[3])
        : "r"(a[0]), "r"(a[1]), "r"(a[2]), "r"(a[3]), "r"(b[0]), "r"(b[1]));
}

// ---- packed f32x2 (FFMA2 path; PTX-only) ----
__device__ __forceinline__ u64 pack2(float lo, float hi) {
    u64 r; asm("mov.b64 %0, {%1, %2};" : "=l"(r) : "f"(lo), "f"(hi)); return r;
}
__device__ __forceinline__ void unpack2(float& lo, float& hi, u64 v) {
    asm("mov.b64 {%0, %1}, %2;" : "=f"(lo), "=f"(hi) : "l"(v));
}
__device__ __forceinline__ u64 mul2(u64 a, u64 b) {
    u64 r; asm("mul.rn.f32x2 %0, %1, %2;" : "=l"(r) : "l"(a), "l"(b)); return r;
}
__device__ __forceinline__ u64 add2(u64 a, u64 b) {
    u64 r; asm("add.rn.f32x2 %0, %1, %2;" : "=l"(r) : "l"(a), "l"(b)); return r;
}
__device__ __forceinline__ u64 fma2(u64 a, u64 b, u64 c) {
    u64 r; asm("fma.rn.f32x2 %0, %1, %2, %3;" : "=l"(r) : "l"(a), "l"(b), "l"(c)); return r;
}

// ---------------------------------------------------------------------------
// Kernel 1: fp32 row norms + fp16 convert. One warp per row.
// ---------------------------------------------------------------------------
__global__ void __launch_bounds__(256)
prep_kernel(const float* __restrict__ query, const float* __restrict__ neigh) {
    int warp = (blockIdx.x * 256 + threadIdx.x) >> 5;   // 0..12287
    int l = threadIdx.x & 31;
    bool isQ = warp < QDIM;
    int r = isQ ? warp : warp - QDIM;
    const float4* src = (const float4*)(isQ ? query + (size_t)r * DDIM
                                            : neigh + (size_t)r * DDIM);
    __half* dst = isQ ? g_A + (size_t)r * DDIM : g_B + (size_t)r * DDIM;

    float4 v0 = src[l * 2];
    float4 v1 = src[l * 2 + 1];

    float s = v0.x * v0.x + v0.y * v0.y + v0.z * v0.z + v0.w * v0.w
            + v1.x * v1.x + v1.y * v1.y + v1.z * v1.z + v1.w * v1.w;

    __half2 h0 = __floats2half2_rn(v0.x, v0.y);
    __half2 h1 = __floats2half2_rn(v0.z, v0.w);
    __half2 h2 = __floats2half2_rn(v1.x, v1.y);
    __half2 h3 = __floats2half2_rn(v1.z, v1.w);
    uint4 pk;
    pk.x = *(uint32_t*)&h0; pk.y = *(uint32_t*)&h1;
    pk.z = *(uint32_t*)&h2; pk.w = *(uint32_t*)&h3;
    ((uint4*)dst)[l] = pk;

#pragma unroll
    for (int off = 16; off > 0; off >>= 1)
        s += __shfl_xor_sync(0xffffffffu, s, off);
    if (l == 0) {
        if (isQ) g_q2[r] = s; else g_n2[r] = s;
    }
}

// ---------------------------------------------------------------------------
// Kernel 2: HMMA fp16 GEMM (128x128 tile, K=256) + smem-prefetched gumbel
// epilogue -> g_w (e = exp(gumbel - dist)). 8 warps 4(M)x2(N); 2 CTAs/SM
// ---------------------------------------------------------------------------
#define A_BYTES (BM * 128)                         // 16 KB
#define B_BYTES (BN * 128)                         // 16 KB
#define STAGE_BYTES (A_BYTES + B_BYTES)            // 32 KB
#define SMEM_DYN (STAGES * STAGE_BYTES)            // 96 KB

__device__ __forceinline__ void load_tile(uint32_t abuf, uint32_t bbuf,
                                          int kt, int qbase, int nbase,
                                          int tid) {
    const char* gA = (const char*)g_A + ((size_t)qbase * DDIM + (size_t)kt * BK) * 2;
    const char* gB = (const char*)g_B + ((size_t)nbase * DDIM + (size_t)kt * BK) * 2;
#pragma unroll
    for (int i = 0; i < 4; ++i) {
        int g = tid * 4 + i;
        int r = g >> 3, ku = g & 7;
        uint32_t so = (uint32_t)(r * 128 + ((ku ^ (r & 7)) << 4));
        cpasync16(abuf + so, gA + (size_t)r * (DDIM * 2) + (size_t)ku * 16);
        cpasync16(bbuf + so, gB + (size_t)r * (DDIM * 2) + (size_t)ku * 16);
    }
}

// gumbel half H (rows H*64..H*64+63 of the 128x128 f32 tile) into one stage.
// Row = 512B; swizzle: byte k*16 -> k*16 ^ ((row&7)<<6). 2048 units, 8/thread.
__device__ __forceinline__ void load_gumbel_half(uint32_t gbuf,
                                                 const float* gsrc,
                                                 int qbase, int nbase, int H,
                                                 int tid) {
#pragma unroll
    for (int i = 0; i < 8; ++i) {
        int u = tid * 8 + i;            // 0..2047
        int row = H * 64 + (u >> 5);    // tile row
        int kk = u & 31;                // 16B unit within 512B row
        uint32_t so = (uint32_t)((row & 63) * 512 + ((kk * 16) ^ ((row & 7) << 6)));
        const float* src = gsrc + (size_t)(qbase + row) * NDIM + nbase + kk * 4;
        cpasync16(gbuf + so, src);
    }
}

__global__ void __launch_bounds__(256, 2)
gemm_kernel(const float* __restrict__ gumbel) {
    extern __shared__ char smem_raw[];
    uint32_t sbase = smem_to_u32(smem_raw);

    int tid = threadIdx.x;
    int wid = tid >> 5;
    int l   = tid & 31;
    int warpm = wid & 3;          // 0..3 -> 32-row slab
    int warpn = wid >> 2;         // 0..1 -> 64-col slab

    int nbase = blockIdx.x * BN;
    int qbase = blockIdx.y * BM;

    uint32_t abuf[STAGES], bbuf[STAGES];
#pragma unroll
    for (int s = 0; s < STAGES; ++s) {
        abuf[s] = sbase + s * STAGE_BYTES;
        bbuf[s] = abuf[s] + A_BYTES;
    }

    load_tile(abuf[0], bbuf[0], 0, qbase, nbase, tid);   // group: t0
    cp_commit();
    load_tile(abuf[1], bbuf[1], 1, qbase, nbase, tid);   // group: t1
    cp_commit();

    float acc[2][8][4];
#pragma unroll
    for (int mt = 0; mt < 2; ++mt)
#pragma unroll
        for (int nt = 0; nt < 8; ++nt)
#pragma unroll
            for (int i = 0; i < 4; ++i) acc[mt][nt][i] = 0.f;

    int a_lr = (l & 15);
    int a_ku = (l >> 4);
    int b_lr = ((l >> 4) << 3) + (l & 7);
    int b_ku = ((l >> 3) & 1);

    // Commit schedule (one group per kt): t2, t3, gumbelA, gumbelB.
    // wait<1> at each kt leaves at most the newest group pending -> the tile
    // needed this kt is always complete.
#pragma unroll
    for (int kt = 0; kt < NKT; ++kt) {
        const int s = kt % STAGES;
        cp_wait<1>();
        __syncthreads();
        if (kt + 2 < NKT) {
            load_tile(abuf[(kt + 2) % STAGES], bbuf[(kt + 2) % STAGES],
                      kt + 2, qbase, nbase, tid);
        } else {
            // stage (kt+2)%3 is dead (its tile consumed at kt-1): kt=2 -> s1,
            // kt=3 -> s2. Prefetch gumbel halves into them.
            load_gumbel_half(abuf[(kt + 2) % STAGES], gumbel,
                             qbase, nbase, kt - 2, tid);
        }
        cp_commit();

        uint32_t aS = abuf[s], bS = bbuf[s];
#pragma unroll
        for (int ks = 0; ks < 4; ++ks) {
            int kb = ks * 2;
            uint32_t afr[2][4];
#pragma unroll
            for (int mt = 0; mt < 2; ++mt) {
                int r = warpm * 32 + mt * 16 + a_lr;
                uint32_t addr = aS + r * 128 + (((kb + a_ku) ^ (r & 7)) << 4);
                ldmatrix_x4(afr[mt], addr);
            }
            uint32_t bfr[4][4];
#pragma unroll
            for (int bt = 0; bt < 4; ++bt) {
                int r = warpn * 64 + bt * 16 + b_lr;
                uint32_t addr = bS + r * 128 + (((kb + b_ku) ^ (r & 7)) << 4);
                ldmatrix_x4(bfr[bt], addr);
            }
#pragma unroll
            for (int mt = 0; mt < 2; ++mt)
#pragma unroll
                for (int nt = 0; nt < 8; ++nt)
                    mma_fp16(acc[mt][nt], afr[mt], &bfr[nt >> 1][(nt & 1) * 2]);
        }
    }
    cp_wait<0>();        // gumbel halves complete
    __syncthreads();     // visible to all threads

    // Fused epilogue: e = exp(gumbel_smem - sqrt(max(q2 + n2 - 2*dot, 0)))
    {
        int lrow0 = warpm * 32 + (l >> 2);            // local tile row
        int lcolb = warpn * 64 + (l & 3) * 2;         // local tile col
#pragma unroll
        for (int mt = 0; mt < 2; ++mt) {
            int lrA = lrow0 + mt * 16;
            int lrB = lrA + 8;
            int rA = qbase + lrA, rB = qbase + lrB;
            float q2a = __ldg(&g_q2[rA]);
            float q2b = __ldg(&g_q2[rB]);
            uint32_t gA_base = abuf[1] + (lrA & 63) * 512;  // s1: rows 0..63
            uint32_t gB_base = abuf[1] + (lrB & 63) * 512;
            if (lrA >= 64) gA_base += STAGE_BYTES;          // s2: rows 64..127
            if (lrB >= 64) gB_base += STAGE_BYTES;
            float2* wA = (float2*)(g_w + (size_t)rA * NDIM + nbase);
            float2* wB = (float2*)(g_w + (size_t)rB * NDIM + nbase);
            int swA = (lrA & 7) << 6, swB = (lrB & 7) << 6;
#pragma unroll
            for (int nt = 0; nt < 8; ++nt) {
                int col = lcolb + nt * 8;
                float n2a = __ldg(&g_n2[nbase + col]);
                float n2b = __ldg(&g_n2[nbase + col + 1]);
                float2 ga = *(const float2*)(smem_raw +
                    (gA_base + (uint32_t)((col * 4) ^ swA) - sbase));
                float2 gb = *(const float2*)(smem_raw +
                    (gB_base + (uint32_t)((col * 4) ^ swB) - sbase));
                float2 oa, ob;
                oa.x = __expf(ga.x - sqrtf(fmaxf(fmaf(-2.f, acc[mt][nt][0], q2a + n2a), 0.f)));
                oa.y = __expf(ga.y - sqrtf(fmaxf(fmaf(-2.f, acc[mt][nt][1], q2a + n2b), 0.f)));
                ob.x = __expf(gb.x - sqrtf(fmaxf(fmaf(-2.f, acc[mt][nt][2], q2b + n2a), 0.f)));
                ob.y = __expf(gb.y - sqrtf(fmaxf(fmaf(-2.f, acc[mt][nt][3], q2b + n2b), 0.f)));
                __stcs(&wA[col >> 1], oa);
                __stcs(&wB[col >> 1], ob);
            }
        }
    }
}

// ---------------------------------------------------------------------------
// Kernel 3: iterative relaxed top-k; one block (256 thr) per query row,
// 32 elems/thread, packed f32x2 math. (R12 verbatim — measured at DRAM floor)
// ---------------------------------------------------------------------------
__global__ void __launch_bounds__(256)
iter_kernel(float* __restrict__ out) {
    __shared__ float sred[2][8];

    int t = threadIdx.x;
    int w = t >> 5, l = t & 31;
    const float4* erow = (const float4*)(g_w + (size_t)blockIdx.x * NDIM);
    float4* orow = (float4*)(out + (size_t)blockIdx.x * NDIM);

    u64 e2[16], kh2[16];
#pragma unroll
    for (int i = 0; i < 8; ++i) {
        float4 v = __ldcs(&erow[i * 256 + t]);
        e2[i * 2 + 0] = pack2(v.x, v.y);
        e2[i * 2 + 1] = pack2(v.z, v.w);
    }
    const u64 zero2 = pack2(0.f, 0.f);
    const u64 none2 = pack2(-1.f, -1.f);
#pragma unroll
    for (int j = 0; j < 16; ++j) kh2[j] = zero2;

#pragma unroll
    for (int it = 0; it < NITER; ++it) {
        int buf = it & 1;
        u64 sa = e2[0], sb = e2[1], sc = e2[2], sd = e2[3];
#pragma unroll
        for (int j = 4; j < 16; j += 4) {
            sa = add2(sa, e2[j]);     sb = add2(sb, e2[j + 1]);
            sc = add2(sc, e2[j + 2]); sd = add2(sd, e2[j + 3]);
        }
        u64 st2 = add2(add2(sa, sb), add2(sc, sd));
        float slo, shi; unpack2(slo, shi, st2);
        float s = slo + shi;
#pragma unroll
        for (int o = 16; o > 0; o >>= 1)
            s += __shfl_xor_sync(0xffffffffu, s, o);
        if (l == 0) sred[buf][w] = s;
        __syncthreads();
        float tot = sred[buf][0];
#pragma unroll
        for (int j = 1; j < 8; ++j) tot += sred[buf][j];
        float ninv = -__fdividef(1.0f, tot);
        u64 ninv2 = pack2(ninv, ninv);
#pragma unroll
        for (int j = 0; j < 16; ++j) {
            u64 np = mul2(e2[j], ninv2);        // np = -p
            kh2[j] = fma2(np, none2, kh2[j]);   // kh += p
            e2[j]  = fma2(np, e2[j], e2[j]);    // e *= (1 - p)
        }
    }

#pragma unroll
    for (int i = 0; i < 8; ++i) {
        float4 o4;
        unpack2(o4.x, o4.y, kh2[i * 2 + 0]);
        unpack2(o4.z, o4.w, kh2[i * 2 + 1]);
        __stcs(&orow[i * 256 + t], o4);
    }
}

// ---------------------------------------------------------------------------
// Launch (serial; overlap impossible: GEMM occupies the full register file)
// ---------------------------------------------------------------------------
extern "C" void kernel_launch(void* const* d_in, const int* in_sizes, int n_in,
                              void* d_out, int out_size) {
    const float* query  = (const float*)d_in[0];   // [4096, 256]
    const float* neigh  = (const float*)d_in[1];   // [1, 8192, 256]
    const float* gumbel = (const float*)d_in[2];   // [4096, 8192]
    float* out = (float*)d_out;                    // [4096, 8192]

    prep_kernel<<<(QDIM + NDIM) / 8, 256>>>(query, neigh);

    cudaFuncSetAttribute(gemm_kernel,
                         cudaFuncAttributeMaxDynamicSharedMemorySize, SMEM_DYN);
    dim3 grid(NDIM / BN, QDIM / BM);
    gemm_kernel<<<grid, 256, SMEM_DYN>>>(gumbel);

    iter_kernel<<<QDIM, 256>>>(out);
}

// round 15
// speedup vs baseline: 1.0104x; 1.0104x over previous
#include <cuda_runtime.h>
#include <cuda_fp16.h>
#include <stdint.h>

// Round 15: revert gumbel prefetch (measured neutral -> R12 epilogue is best),
// prep does 2 rows/warp (launch-latency bound, fewer blocks), iter skips the
// dead last-iteration e-update. Decomposition is at its structural floor:
// prep ~5 + GEMM ~150 (legacy mma.sync issue ceiling) + iter ~35 (HBM spec).

// ---------------------------------------------------------------------------
#define QDIM   4096
#define NDIM   8192
#define DDIM   256
#define BM     128
#define BN     128
#define BK     64
#define NKT    4            // 256/64
#define STAGES 3
#define NITER  10

typedef unsigned long long u64;

// ---------------------------------------------------------------------------
// Device scratch (no allocation allowed)
// ---------------------------------------------------------------------------
__device__ __align__(128) __half g_A[(size_t)QDIM * DDIM];            // 2 MB
__device__ __align__(128) __half g_B[(size_t)NDIM * DDIM];            // 4 MB
__device__ __align__(128) float g_q2[QDIM];
__device__ __align__(128) float g_n2[NDIM];
__device__ __align__(128) float g_w[(size_t)QDIM * NDIM];             // 128 MB (stores e=exp(w))

// ---------------------------------------------------------------------------
// PTX helpers
// ---------------------------------------------------------------------------
__device__ __forceinline__ uint32_t smem_to_u32(const void* p) {
    uint32_t a;
    asm("{ .reg .u64 t; cvta.to.shared.u64 t, %1; cvt.u32.u64 %0, t; }"
        : "=r"(a) : "l"(p));
    return a;
}

__device__ __forceinline__ void cpasync16(uint32_t dst, const void* src) {
    asm volatile("cp.async.cg.shared.global [%0], [%1], 16;"
                 :: "r"(dst), "l"(src) : "memory");
}
__device__ __forceinline__ void cp_commit() {
    asm volatile("cp.async.commit_group;" ::: "memory");
}
template <int N> __device__ __forceinline__ void cp_wait() {
    asm volatile("cp.async.wait_group %0;" :: "n"(N) : "memory");
}

__device__ __forceinline__ void ldmatrix_x4(uint32_t* r, uint32_t addr) {
    asm volatile("ldmatrix.sync.aligned.m8n8.x4.shared.b16 {%0,%1,%2,%3}, [%4];"
                 : "=r"(r[0]), "=r"(r[1]), "=r"(r[2]), "=r"(r[3]) : "r"(addr));
}

__device__ __forceinline__ void mma_fp16(float* c, const uint32_t* a,
                                         const uint32_t* b) {
    asm volatile(
        "mma.sync.aligned.m16n8k16.row.col.f32.f16.f16.f32 "
        "{%0,%1,%2,%3}, {%4,%5,%6,%7}, {%8,%9}, {%0,%1,%2,%3};"
        : "+f"(c[0]), "+f"(c[1]), "+f"(c[2]), "+f"(c[3])
        : "r"(a[0]), "r"(a[1]), "r"(a[2]), "r"(a[3]), "r"(b[0]), "r"(b[1]));
}

// ---- packed f32x2 (FFMA2 path; PTX-only) ----
__device__ __forceinline__ u64 pack2(float lo, float hi) {
    u64 r; asm("mov.b64 %0, {%1, %2};" : "=l"(r) : "f"(lo), "f"(hi)); return r;
}
__device__ __forceinline__ void unpack2(float& lo, float& hi, u64 v) {
    asm("mov.b64 {%0, %1}, %2;" : "=f"(lo), "=f"(hi) : "l"(v));
}
__device__ __forceinline__ u64 mul2(u64 a, u64 b) {
    u64 r; asm("mul.rn.f32x2 %0, %1, %2;" : "=l"(r) : "l"(a), "l"(b)); return r;
}
__device__ __forceinline__ u64 add2(u64 a, u64 b) {
    u64 r; asm("add.rn.f32x2 %0, %1, %2;" : "=l"(r) : "l"(a), "l"(b)); return r;
}
__device__ __forceinline__ u64 fma2(u64 a, u64 b, u64 c) {
    u64 r; asm("fma.rn.f32x2 %0, %1, %2, %3;" : "=l"(r) : "l"(a), "l"(b), "l"(c)); return r;
}

// ---------------------------------------------------------------------------
// Kernel 1: fp32 row norms + fp16 convert. TWO rows per warp.
// grid = (QDIM+NDIM)/16 = 768 blocks of 256 threads
// ---------------------------------------------------------------------------
__global__ void __launch_bounds__(256)
prep_kernel(const float* __restrict__ query, const float* __restrict__ neigh) {
    int warp0 = (blockIdx.x * 256 + threadIdx.x) >> 5;   // 0..6143
    int l = threadIdx.x & 31;

#pragma unroll
    for (int k = 0; k < 2; ++k) {
        int row = warp0 * 2 + k;                          // 0..12287
        bool isQ = row < QDIM;
        int r = isQ ? row : row - QDIM;
        const float4* src = (const float4*)(isQ ? query + (size_t)r * DDIM
                                                : neigh + (size_t)r * DDIM);
        __half* dst = isQ ? g_A + (size_t)r * DDIM : g_B + (size_t)r * DDIM;

        float4 v0 = src[l * 2];
        float4 v1 = src[l * 2 + 1];

        float s = v0.x * v0.x + v0.y * v0.y + v0.z * v0.z + v0.w * v0.w
                + v1.x * v1.x + v1.y * v1.y + v1.z * v1.z + v1.w * v1.w;

        __half2 h0 = __floats2half2_rn(v0.x, v0.y);
        __half2 h1 = __floats2half2_rn(v0.z, v0.w);
        __half2 h2 = __floats2half2_rn(v1.x, v1.y);
        __half2 h3 = __floats2half2_rn(v1.z, v1.w);
        uint4 pk;
        pk.x = *(uint32_t*)&h0; pk.y = *(uint32_t*)&h1;
        pk.z = *(uint32_t*)&h2; pk.w = *(uint32_t*)&h3;
        ((uint4*)dst)[l] = pk;

#pragma unroll
        for (int off = 16; off > 0; off >>= 1)
            s += __shfl_xor_sync(0xffffffffu, s, off);
        if (l == 0) {
            if (isQ) g_q2[r] = s; else g_n2[r] = s;
        }
    }
}

// ---------------------------------------------------------------------------
// Kernel 2: HMMA fp16 GEMM (128x128 tile, K=256) + fused epilogue -> g_w
// stores e = exp(gumbel - dist). 8 warps 4(M)x2(N); 2 CTAs/SM  (R12 verbatim)
// ---------------------------------------------------------------------------
#define A_BYTES (BM * 128)                         // 16 KB
#define B_BYTES (BN * 128)                         // 16 KB
#define STAGE_BYTES (A_BYTES + B_BYTES)            // 32 KB
#define SMEM_DYN (STAGES * STAGE_BYTES)            // 96 KB

__device__ __forceinline__ void load_tile(uint32_t abuf, uint32_t bbuf,
                                          int kt, int qbase, int nbase,
                                          int tid) {
    const char* gA = (const char*)g_A + ((size_t)qbase * DDIM + (size_t)kt * BK) * 2;
    const char* gB = (const char*)g_B + ((size_t)nbase * DDIM + (size_t)kt * BK) * 2;
#pragma unroll
    for (int i = 0; i < 4; ++i) {
        int g = tid * 4 + i;
        int r = g >> 3, ku = g & 7;
        uint32_t so = (uint32_t)(r * 128 + ((ku ^ (r & 7)) << 4));
        cpasync16(abuf + so, gA + (size_t)r * (DDIM * 2) + (size_t)ku * 16);
        cpasync16(bbuf + so, gB + (size_t)r * (DDIM * 2) + (size_t)ku * 16);
    }
}

__global__ void __launch_bounds__(256, 2)
gemm_kernel(const float* __restrict__ gumbel) {
    extern __shared__ char smem_raw[];
    uint32_t sbase = smem_to_u32(smem_raw);

    int tid = threadIdx.x;
    int wid = tid >> 5;
    int l   = tid & 31;
    int warpm = wid & 3;          // 0..3 -> 32-row slab
    int warpn = wid >> 2;         // 0..1 -> 64-col slab

    int nbase = blockIdx.x * BN;
    int qbase = blockIdx.y * BM;

    uint32_t abuf[STAGES], bbuf[STAGES];
#pragma unroll
    for (int s = 0; s < STAGES; ++s) {
        abuf[s] = sbase + s * STAGE_BYTES;
        bbuf[s] = abuf[s] + A_BYTES;
    }

    load_tile(abuf[0], bbuf[0], 0, qbase, nbase, tid);
    cp_commit();
    load_tile(abuf[1], bbuf[1], 1, qbase, nbase, tid);
    cp_commit();

    float acc[2][8][4];
#pragma unroll
    for (int mt = 0; mt < 2; ++mt)
#pragma unroll
        for (int nt = 0; nt < 8; ++nt)
#pragma unroll
            for (int i = 0; i < 4; ++i) acc[mt][nt][i] = 0.f;

    int a_lr = (l & 15);
    int a_ku = (l >> 4);
    int b_lr = ((l >> 4) << 3) + (l & 7);
    int b_ku = ((l >> 3) & 1);

#pragma unroll
    for (int kt = 0; kt < NKT; ++kt) {
        const int s = kt % STAGES;
        if (kt < NKT - 1) cp_wait<1>();
        else              cp_wait<0>();
        __syncthreads();
        if (kt + 2 < NKT) {
            load_tile(abuf[(kt + 2) % STAGES], bbuf[(kt + 2) % STAGES],
                      kt + 2, qbase, nbase, tid);
            cp_commit();
        }

        uint32_t aS = abuf[s], bS = bbuf[s];
#pragma unroll
        for (int ks = 0; ks < 4; ++ks) {
            int kb = ks * 2;
            uint32_t afr[2][4];
#pragma unroll
            for (int mt = 0; mt < 2; ++mt) {
                int r = warpm * 32 + mt * 16 + a_lr;
                uint32_t addr = aS + r * 128 + (((kb + a_ku) ^ (r & 7)) << 4);
                ldmatrix_x4(afr[mt], addr);
            }
            uint32_t bfr[4][4];
#pragma unroll
            for (int bt = 0; bt < 4; ++bt) {
                int r = warpn * 64 + bt * 16 + b_lr;
                uint32_t addr = bS + r * 128 + (((kb + b_ku) ^ (r & 7)) << 4);
                ldmatrix_x4(bfr[bt], addr);
            }
#pragma unroll
            for (int mt = 0; mt < 2; ++mt)
#pragma unroll
                for (int nt = 0; nt < 8; ++nt)
                    mma_fp16(acc[mt][nt], afr[mt], &bfr[nt >> 1][(nt & 1) * 2]);
        }
    }

    // Fused epilogue: e = exp(gumbel - sqrt(max(q2 + n2 - 2*dot, 0)))
    {
        int row0 = qbase + warpm * 32 + (l >> 2);
        int colb = nbase + warpn * 64 + (l & 3) * 2;
#pragma unroll
        for (int mt = 0; mt < 2; ++mt) {
            int rA = row0 + mt * 16;
            int rB = rA + 8;
            float q2a = __ldg(&g_q2[rA]);
            float q2b = __ldg(&g_q2[rB]);
            const float2* gAraw = (const float2*)(gumbel + (size_t)rA * NDIM);
            const float2* gBraw = (const float2*)(gumbel + (size_t)rB * NDIM);
            float2* wA = (float2*)(g_w + (size_t)rA * NDIM);
            float2* wB = (float2*)(g_w + (size_t)rB * NDIM);
#pragma unroll
            for (int nt = 0; nt < 8; ++nt) {
                int col = colb + nt * 8;
                float n2a = __ldg(&g_n2[col]);
                float n2b = __ldg(&g_n2[col + 1]);
                float2 ga = __ldcs(&gAraw[col >> 1]);
                float2 gb = __ldcs(&gBraw[col >> 1]);
                float2 oa, ob;
                oa.x = __expf(ga.x - sqrtf(fmaxf(fmaf(-2.f, acc[mt][nt][0], q2a + n2a), 0.f)));
                oa.y = __expf(ga.y - sqrtf(fmaxf(fmaf(-2.f, acc[mt][nt][1], q2a + n2b), 0.f)));
                ob.x = __expf(gb.x - sqrtf(fmaxf(fmaf(-2.f, acc[mt][nt][2], q2b + n2a), 0.f)));
                ob.y = __expf(gb.y - sqrtf(fmaxf(fmaf(-2.f, acc[mt][nt][3], q2b + n2b), 0.f)));
                __stcs(&wA[col >> 1], oa);
                __stcs(&wB[col >> 1], ob);
            }
        }
    }
}

// ---------------------------------------------------------------------------
// Kernel 3: iterative relaxed top-k; one block (256 thr) per query row,
// 32 elems/thread, packed f32x2 math. Last-iteration e-update skipped (dead).
// ---------------------------------------------------------------------------
__global__ void __launch_bounds__(256)
iter_kernel(float* __restrict__ out) {
    __shared__ float sred[2][8];

    int t = threadIdx.x;
    int w = t >> 5, l = t & 31;
    const float4* erow = (const float4*)(g_w + (size_t)blockIdx.x * NDIM);
    float4* orow = (float4*)(out + (size_t)blockIdx.x * NDIM);

    u64 e2[16], kh2[16];
#pragma unroll
    for (int i = 0; i < 8; ++i) {
        float4 v = __ldcs(&erow[i * 256 + t]);
        e2[i * 2 + 0] = pack2(v.x, v.y);
        e2[i * 2 + 1] = pack2(v.z, v.w);
    }
    const u64 zero2 = pack2(0.f, 0.f);
    const u64 none2 = pack2(-1.f, -1.f);
#pragma unroll
    for (int j = 0; j < 16; ++j) kh2[j] = zero2;

#pragma unroll
    for (int it = 0; it < NITER; ++it) {
        int buf = it & 1;
        u64 sa = e2[0], sb = e2[1], sc = e2[2], sd = e2[3];
#pragma unroll
        for (int j = 4; j < 16; j += 4) {
            sa = add2(sa, e2[j]);     sb = add2(sb, e2[j + 1]);
            sc = add2(sc, e2[j + 2]); sd = add2(sd, e2[j + 3]);
        }
        u64 st2 = add2(add2(sa, sb), add2(sc, sd));
        float slo, shi; unpack2(slo, shi, st2);
        float s = slo + shi;
#pragma unroll
        for (int o = 16; o > 0; o >>= 1)
            s += __shfl_xor_sync(0xffffffffu, s, o);
        if (l == 0) sred[buf][w] = s;
        __syncthreads();
        float tot = sred[buf][0];
#pragma unroll
        for (int j = 1; j < 8; ++j) tot += sred[buf][j];
        float ninv = -__fdividef(1.0f, tot);
        u64 ninv2 = pack2(ninv, ninv);
        if (it < NITER - 1) {
#pragma unroll
            for (int j = 0; j < 16; ++j) {
                u64 np = mul2(e2[j], ninv2);        // np = -p
                kh2[j] = fma2(np, none2, kh2[j]);   // kh += p
                e2[j]  = fma2(np, e2[j], e2[j]);    // e *= (1 - p)
            }
        } else {
#pragma unroll
            for (int j = 0; j < 16; ++j) {
                u64 np = mul2(e2[j], ninv2);        // np = -p
                kh2[j] = fma2(np, none2, kh2[j]);   // kh += p (e update dead)
            }
        }
    }

#pragma unroll
    for (int i = 0; i < 8; ++i) {
        float4 o4;
        unpack2(o4.x, o4.y, kh2[i * 2 + 0]);
        unpack2(o4.z, o4.w, kh2[i * 2 + 1]);
        __stcs(&orow[i * 256 + t], o4);
    }
}

// ---------------------------------------------------------------------------
// Launch (serial; overlap impossible: GEMM occupies the full register file)
// ---------------------------------------------------------------------------
extern "C" void kernel_launch(void* const* d_in, const int* in_sizes, int n_in,
                              void* d_out, int out_size) {
    const float* query  = (const float*)d_in[0];   // [4096, 256]
    const float* neigh  = (const float*)d_in[1];   // [1, 8192, 256]
    const float* gumbel = (const float*)d_in[2];   // [4096, 8192]
    float* out = (float*)d_out;                    // [4096, 8192]

    prep_kernel<<<(QDIM + NDIM) / 16, 256>>>(query, neigh);

    cudaFuncSetAttribute(gemm_kernel,
                         cudaFuncAttributeMaxDynamicSharedMemorySize, SMEM_DYN);
    dim3 grid(NDIM / BN, QDIM / BM);
    gemm_kernel<<<grid, 256, SMEM_DYN>>>(gumbel);

    iter_kernel<<<QDIM, 256>>>(out);
}

// round 16
// speedup vs baseline: 1.0654x; 1.0544x over previous
#include <cuda_runtime.h>
#include <cuda_fp16.h>
#include <stdint.h>

// Round 16: force sqrt.approx.f32 in the GEMM epilogue (1 MUFU op instead of
// the IEEE software-sqrt sequence if the harness lacks --use_fast_math).
// Epilogue MUFU serialization across 16 warps/SM x 7 waves accounts for most
// of the ~20us gap between GEMM (152us) and its pure-MMA floor (~129us).
// Everything else kept: R15 structure measured at the decomposition floor.

// ---------------------------------------------------------------------------
#define QDIM   4096
#define NDIM   8192
#define DDIM   256
#define BM     128
#define BN     128
#define BK     64
#define NKT    4            // 256/64
#define STAGES 3
#define NITER  10

typedef unsigned long long u64;

// ---------------------------------------------------------------------------
// Device scratch (no allocation allowed)
// ---------------------------------------------------------------------------
__device__ __align__(128) __half g_A[(size_t)QDIM * DDIM];            // 2 MB
__device__ __align__(128) __half g_B[(size_t)NDIM * DDIM];            // 4 MB
__device__ __align__(128) float g_q2[QDIM];
__device__ __align__(128) float g_n2[NDIM];
__device__ __align__(128) float g_w[(size_t)QDIM * NDIM];             // 128 MB (stores e=exp(w))

// ---------------------------------------------------------------------------
// PTX helpers
// ---------------------------------------------------------------------------
__device__ __forceinline__ uint32_t smem_to_u32(const void* p) {
    uint32_t a;
    asm("{ .reg .u64 t; cvta.to.shared.u64 t, %1; cvt.u32.u64 %0, t; }"
        : "=r"(a) : "l"(p));
    return a;
}

__device__ __forceinline__ void cpasync16(uint32_t dst, const void* src) {
    asm volatile("cp.async.cg.shared.global [%0], [%1], 16;"
                 :: "r"(dst), "l"(src) : "memory");
}
__device__ __forceinline__ void cp_commit() {
    asm volatile("cp.async.commit_group;" ::: "memory");
}
template <int N> __device__ __forceinline__ void cp_wait() {
    asm volatile("cp.async.wait_group %0;" :: "n"(N) : "memory");
}

__device__ __forceinline__ void ldmatrix_x4(uint32_t* r, uint32_t addr) {
    asm volatile("ldmatrix.sync.aligned.m8n8.x4.shared.b16 {%0,%1,%2,%3}, [%4];"
                 : "=r"(r[0]), "=r"(r[1]), "=r"(r[2]), "=r"(r[3]) : "r"(addr));
}

__device__ __forceinline__ void mma_fp16(float* c, const uint32_t* a,
                                         const uint32_t* b) {
    asm volatile(
        "mma.sync.aligned.m16n8k16.row.col.f32.f16.f16.f32 "
        "{%0,%1,%2,%3}, {%4,%5,%6,%7}, {%8,%9}, {%0,%1,%2,%3};"
        : "+f"(c[0]), "+f"(c[1]), "+f"(c[2]), "+f"(c[3])
        : "r"(a[0]), "r"(a[1]), "r"(a[2]), "r"(a[3]), "r"(b[0]), "r"(b[1]));
}

// 1-MUFU approximate sqrt (independent of harness fast-math flags).
// sqrt.approx(0) = 0, so the fmaxf(...,0) clamp stays NaN-safe.
__device__ __forceinline__ float fsqrt_approx(float x) {
    float r;
    asm("sqrt.approx.f32 %0, %1;" : "=f"(r) : "f"(x));
    return r;
}

// ---- packed f32x2 (FFMA2 path; PTX-only) ----
__device__ __forceinline__ u64 pack2(float lo, float hi) {
    u64 r; asm("mov.b64 %0, {%1, %2};" : "=l"(r) : "f"(lo), "f"(hi)); return r;
}
__device__ __forceinline__ void unpack2(float& lo, float& hi, u64 v) {
    asm("mov.b64 {%0, %1}, %2;" : "=f"(lo), "=f"(hi) : "l"(v));
}
__device__ __forceinline__ u64 mul2(u64 a, u64 b) {
    u64 r; asm("mul.rn.f32x2 %0, %1, %2;" : "=l"(r) : "l"(a), "l"(b)); return r;
}
__device__ __forceinline__ u64 add2(u64 a, u64 b) {
    u64 r; asm("add.rn.f32x2 %0, %1, %2;" : "=l"(r) : "l"(a), "l"(b)); return r;
}
__device__ __forceinline__ u64 fma2(u64 a, u64 b, u64 c) {
    u64 r; asm("fma.rn.f32x2 %0, %1, %2, %3;" : "=l"(r) : "l"(a), "l"(b), "l"(c)); return r;
}

// ---------------------------------------------------------------------------
// Kernel 1: fp32 row norms + fp16 convert. TWO rows per warp.
// grid = (QDIM+NDIM)/16 = 768 blocks of 256 threads
// ---------------------------------------------------------------------------
__global__ void __launch_bounds__(256)
prep_kernel(const float* __restrict__ query, const float* __restrict__ neigh) {
    int warp0 = (blockIdx.x * 256 + threadIdx.x) >> 5;   // 0..6143
    int l = threadIdx.x & 31;

#pragma unroll
    for (int k = 0; k < 2; ++k) {
        int row = warp0 * 2 + k;                          // 0..12287
        bool isQ = row < QDIM;
        int r = isQ ? row : row - QDIM;
        const float4* src = (const float4*)(isQ ? query + (size_t)r * DDIM
                                                : neigh + (size_t)r * DDIM);
        __half* dst = isQ ? g_A + (size_t)r * DDIM : g_B + (size_t)r * DDIM;

        float4 v0 = src[l * 2];
        float4 v1 = src[l * 2 + 1];

        float s = v0.x * v0.x + v0.y * v0.y + v0.z * v0.z + v0.w * v0.w
                + v1.x * v1.x + v1.y * v1.y + v1.z * v1.z + v1.w * v1.w;

        __half2 h0 = __floats2half2_rn(v0.x, v0.y);
        __half2 h1 = __floats2half2_rn(v0.z, v0.w);
        __half2 h2 = __floats2half2_rn(v1.x, v1.y);
        __half2 h3 = __floats2half2_rn(v1.z, v1.w);
        uint4 pk;
        pk.x = *(uint32_t*)&h0; pk.y = *(uint32_t*)&h1;
        pk.z = *(uint32_t*)&h2; pk.w = *(uint32_t*)&h3;
        ((uint4*)dst)[l] = pk;

#pragma unroll
        for (int off = 16; off > 0; off >>= 1)
            s += __shfl_xor_sync(0xffffffffu, s, off);
        if (l == 0) {
            if (isQ) g_q2[r] = s; else g_n2[r] = s;
        }
    }
}

// ---------------------------------------------------------------------------
// Kernel 2: HMMA fp16 GEMM (128x128 tile, K=256) + fused epilogue -> g_w
// stores e = exp(gumbel - dist). 8 warps 4(M)x2(N); 2 CTAs/SM
// ---------------------------------------------------------------------------
#define A_BYTES (BM * 128)                         // 16 KB
#define B_BYTES (BN * 128)                         // 16 KB
#define STAGE_BYTES (A_BYTES + B_BYTES)            // 32 KB
#define SMEM_DYN (STAGES * STAGE_BYTES)            // 96 KB

__device__ __forceinline__ void load_tile(uint32_t abuf, uint32_t bbuf,
                                          int kt, int qbase, int nbase,
                                          int tid) {
    const char* gA = (const char*)g_A + ((size_t)qbase * DDIM + (size_t)kt * BK) * 2;
    const char* gB = (const char*)g_B + ((size_t)nbase * DDIM + (size_t)kt * BK) * 2;
#pragma unroll
    for (int i = 0; i < 4; ++i) {
        int g = tid * 4 + i;
        int r = g >> 3, ku = g & 7;
        uint32_t so = (uint32_t)(r * 128 + ((ku ^ (r & 7)) << 4));
        cpasync16(abuf + so, gA + (size_t)r * (DDIM * 2) + (size_t)ku * 16);
        cpasync16(bbuf + so, gB + (size_t)r * (DDIM * 2) + (size_t)ku * 16);
    }
}

__global__ void __launch_bounds__(256, 2)
gemm_kernel(const float* __restrict__ gumbel) {
    extern __shared__ char smem_raw[];
    uint32_t sbase = smem_to_u32(smem_raw);

    int tid = threadIdx.x;
    int wid = tid >> 5;
    int l   = tid & 31;
    int warpm = wid & 3;          // 0..3 -> 32-row slab
    int warpn = wid >> 2;         // 0..1 -> 64-col slab

    int nbase = blockIdx.x * BN;
    int qbase = blockIdx.y * BM;

    uint32_t abuf[STAGES], bbuf[STAGES];
#pragma unroll
    for (int s = 0; s < STAGES; ++s) {
        abuf[s] = sbase + s * STAGE_BYTES;
        bbuf[s] = abuf[s] + A_BYTES;
    }

    load_tile(abuf[0], bbuf[0], 0, qbase, nbase, tid);
    cp_commit();
    load_tile(abuf[1], bbuf[1], 1, qbase, nbase, tid);
    cp_commit();

    float acc[2][8][4];
#pragma unroll
    for (int mt = 0; mt < 2; ++mt)
#pragma unroll
        for (int nt = 0; nt < 8; ++nt)
#pragma unroll
            for (int i = 0; i < 4; ++i) acc[mt][nt][i] = 0.f;

    int a_lr = (l & 15);
    int a_ku = (l >> 4);
    int b_lr = ((l >> 4) << 3) + (l & 7);
    int b_ku = ((l >> 3) & 1);

#pragma unroll
    for (int kt = 0; kt < NKT; ++kt) {
        const int s = kt % STAGES;
        if (kt < NKT - 1) cp_wait<1>();
        else              cp_wait<0>();
        __syncthreads();
        if (kt + 2 < NKT) {
            load_tile(abuf[(kt + 2) % STAGES], bbuf[(kt + 2) % STAGES],
                      kt + 2, qbase, nbase, tid);
            cp_commit();
        }

        uint32_t aS = abuf[s], bS = bbuf[s];
#pragma unroll
        for (int ks = 0; ks < 4; ++ks) {
            int kb = ks * 2;
            uint32_t afr[2][4];
#pragma unroll
            for (int mt = 0; mt < 2; ++mt) {
                int r = warpm * 32 + mt * 16 + a_lr;
                uint32_t addr = aS + r * 128 + (((kb + a_ku) ^ (r & 7)) << 4);
                ldmatrix_x4(afr[mt], addr);
            }
            uint32_t bfr[4][4];
#pragma unroll
            for (int bt = 0; bt < 4; ++bt) {
                int r = warpn * 64 + bt * 16 + b_lr;
                uint32_t addr = bS + r * 128 + (((kb + b_ku) ^ (r & 7)) << 4);
                ldmatrix_x4(bfr[bt], addr);
            }
#pragma unroll
            for (int mt = 0; mt < 2; ++mt)
#pragma unroll
                for (int nt = 0; nt < 8; ++nt)
                    mma_fp16(acc[mt][nt], afr[mt], &bfr[nt >> 1][(nt & 1) * 2]);
        }
    }

    // Fused epilogue: e = exp(gumbel - sqrt.approx(max(q2 + n2 - 2*dot, 0)))
    {
        int row0 = qbase + warpm * 32 + (l >> 2);
        int colb = nbase + warpn * 64 + (l & 3) * 2;
#pragma unroll
        for (int mt = 0; mt < 2; ++mt) {
            int rA = row0 + mt * 16;
            int rB = rA + 8;
            float q2a = __ldg(&g_q2[rA]);
            float q2b = __ldg(&g_q2[rB]);
            const float2* gAraw = (const float2*)(gumbel + (size_t)rA * NDIM);
            const float2* gBraw = (const float2*)(gumbel + (size_t)rB * NDIM);
            float2* wA = (float2*)(g_w + (size_t)rA * NDIM);
            float2* wB = (float2*)(g_w + (size_t)rB * NDIM);
#pragma unroll
            for (int nt = 0; nt < 8; ++nt) {
                int col = colb + nt * 8;
                float n2a = __ldg(&g_n2[col]);
                float n2b = __ldg(&g_n2[col + 1]);
                float2 ga = __ldcs(&gAraw[col >> 1]);
                float2 gb = __ldcs(&gBraw[col >> 1]);
                float2 oa, ob;
                oa.x = __expf(ga.x - fsqrt_approx(fmaxf(fmaf(-2.f, acc[mt][nt][0], q2a + n2a), 0.f)));
                oa.y = __expf(ga.y - fsqrt_approx(fmaxf(fmaf(-2.f, acc[mt][nt][1], q2a + n2b), 0.f)));
                ob.x = __expf(gb.x - fsqrt_approx(fmaxf(fmaf(-2.f, acc[mt][nt][2], q2b + n2a), 0.f)));
                ob.y = __expf(gb.y - fsqrt_approx(fmaxf(fmaf(-2.f, acc[mt][nt][3], q2b + n2b), 0.f)));
                __stcs(&wA[col >> 1], oa);
                __stcs(&wB[col >> 1], ob);
            }
        }
    }
}

// ---------------------------------------------------------------------------
// Kernel 3: iterative relaxed top-k; one block (256 thr) per query row,
// 32 elems/thread, packed f32x2 math. Last-iteration e-update skipped (dead).
// ---------------------------------------------------------------------------
__global__ void __launch_bounds__(256)
iter_kernel(float* __restrict__ out) {
    __shared__ float sred[2][8];

    int t = threadIdx.x;
    int w = t >> 5, l = t & 31;
    const float4* erow = (const float4*)(g_w + (size_t)blockIdx.x * NDIM);
    float4* orow = (float4*)(out + (size_t)blockIdx.x * NDIM);

    u64 e2[16], kh2[16];
#pragma unroll
    for (int i = 0; i < 8; ++i) {
        float4 v = __ldcs(&erow[i * 256 + t]);
        e2[i * 2 + 0] = pack2(v.x, v.y);
        e2[i * 2 + 1] = pack2(v.z, v.w);
    }
    const u64 zero2 = pack2(0.f, 0.f);
    const u64 none2 = pack2(-1.f, -1.f);
#pragma unroll
    for (int j = 0; j < 16; ++j) kh2[j] = zero2;

#pragma unroll
    for (int it = 0; it < NITER; ++it) {
        int buf = it & 1;
        u64 sa = e2[0], sb = e2[1], sc = e2[2], sd = e2[3];
#pragma unroll
        for (int j = 4; j < 16; j += 4) {
            sa = add2(sa, e2[j]);     sb = add2(sb, e2[j + 1]);
            sc = add2(sc, e2[j + 2]); sd = add2(sd, e2[j + 3]);
        }
        u64 st2 = add2(add2(sa, sb), add2(sc, sd));
        float slo, shi; unpack2(slo, shi, st2);
        float s = slo + shi;
#pragma unroll
        for (int o = 16; o > 0; o >>= 1)
            s += __shfl_xor_sync(0xffffffffu, s, o);
        if (l == 0) sred[buf][w] = s;
        __syncthreads();
        float tot = sred[buf][0];
#pragma unroll
        for (int j = 1; j < 8; ++j) tot += sred[buf][j];
        float ninv = -__fdividef(1.0f, tot);
        u64 ninv2 = pack2(ninv, ninv);
        if (it < NITER - 1) {
#pragma unroll
            for (int j = 0; j < 16; ++j) {
                u64 np = mul2(e2[j], ninv2);        // np = -p
                kh2[j] = fma2(np, none2, kh2[j]);   // kh += p
                e2[j]  = fma2(np, e2[j], e2[j]);    // e *= (1 - p)
            }
        } else {
#pragma unroll
            for (int j = 0; j < 16; ++j) {
                u64 np = mul2(e2[j], ninv2);        // np = -p
                kh2[j] = fma2(np, none2, kh2[j]);   // kh += p (e update dead)
            }
        }
    }

#pragma unroll
    for (int i = 0; i < 8; ++i) {
        float4 o4;
        unpack2(o4.x, o4.y, kh2[i * 2 + 0]);
        unpack2(o4.z, o4.w, kh2[i * 2 + 1]);
        __stcs(&orow[i * 256 + t], o4);
    }
}

// ---------------------------------------------------------------------------
// Launch (serial; overlap impossible: GEMM occupies the full register file)
// ---------------------------------------------------------------------------
extern "C" void kernel_launch(void* const* d_in, const int* in_sizes, int n_in,
                              void* d_out, int out_size) {
    const float* query  = (const float*)d_in[0];   // [4096, 256]
    const float* neigh  = (const float*)d_in[1];   // [1, 8192, 256]
    const float* gumbel = (const float*)d_in[2];   // [4096, 8192]
    float* out = (float*)d_out;                    // [4096, 8192]

    prep_kernel<<<(QDIM + NDIM) / 16, 256>>>(query, neigh);

    cudaFuncSetAttribute(gemm_kernel,
                         cudaFuncAttributeMaxDynamicSharedMemorySize, SMEM_DYN);
    dim3 grid(NDIM / BN, QDIM / BM);
    gemm_kernel<<<grid, 256, SMEM_DYN>>>(gumbel);

    iter_kernel<<<QDIM, 256>>>(out);
}

// round 17
// speedup vs baseline: 1.0702x; 1.0045x over previous
#include <cuda_runtime.h>
#include <cuda_fp16.h>
#include <stdint.h>

// Round 17: mainloop reorder — ks=0 compute issues immediately after the
// barrier; the next-tile cp.async burst (8 LDGSTS/thread, ~64 issue-cyc/warp)
// is moved between ks=0 and ks=1 so it overlaps HMMA instead of delaying it.
// R16 state otherwise frozen (sqrt.approx epilogue, f32x2 iter, 2-rows/warp
// prep): prep ~7 + GEMM ~142 + iter ~35 (HBM floor) + gaps ~3.

// ---------------------------------------------------------------------------
#define QDIM   4096
#define NDIM   8192
#define DDIM   256
#define BM     128
#define BN     128
#define BK     64
#define NKT    4            // 256/64
#define STAGES 3
#define NITER  10

typedef unsigned long long u64;

// ---------------------------------------------------------------------------
// Device scratch (no allocation allowed)
// ---------------------------------------------------------------------------
__device__ __align__(128) __half g_A[(size_t)QDIM * DDIM];            // 2 MB
__device__ __align__(128) __half g_B[(size_t)NDIM * DDIM];            // 4 MB
__device__ __align__(128) float g_q2[QDIM];
__device__ __align__(128) float g_n2[NDIM];
__device__ __align__(128) float g_w[(size_t)QDIM * NDIM];             // 128 MB (stores e=exp(w))

// ---------------------------------------------------------------------------
// PTX helpers
// ---------------------------------------------------------------------------
__device__ __forceinline__ uint32_t smem_to_u32(const void* p) {
    uint32_t a;
    asm("{ .reg .u64 t; cvta.to.shared.u64 t, %1; cvt.u32.u64 %0, t; }"
        : "=r"(a) : "l"(p));
    return a;
}

__device__ __forceinline__ void cpasync16(uint32_t dst, const void* src) {
    asm volatile("cp.async.cg.shared.global [%0], [%1], 16;"
                 :: "r"(dst), "l"(src) : "memory");
}
__device__ __forceinline__ void cp_commit() {
    asm volatile("cp.async.commit_group;" ::: "memory");
}
template <int N> __device__ __forceinline__ void cp_wait() {
    asm volatile("cp.async.wait_group %0;" :: "n"(N) : "memory");
}

__device__ __forceinline__ void ldmatrix_x4(uint32_t* r, uint32_t addr) {
    asm volatile("ldmatrix.sync.aligned.m8n8.x4.shared.b16 {%0,%1,%2,%3}, [%4];"
                 : "=r"(r[0]), "=r"(r[1]), "=r"(r[2]), "=r"(r[3]) : "r"(addr));
}

__device__ __forceinline__ void mma_fp16(float* c, const uint32_t* a,
                                         const uint32_t* b) {
    asm volatile(
        "mma.sync.aligned.m16n8k16.row.col.f32.f16.f16.f32 "
        "{%0,%1,%2,%3}, {%4,%5,%6,%7}, {%8,%9}, {%0,%1,%2,%3};"
        : "+f"(c[0]), "+f"(c[1]), "+f"(c[2]), "+f"(c[3])
        : "r"(a[0]), "r"(a[1]), "r"(a[2]), "r"(a[3]), "r"(b[0]), "r"(b[1]));
}

// 1-MUFU approximate sqrt (independent of harness fast-math flags).
__device__ __forceinline__ float fsqrt_approx(float x) {
    float r;
    asm("sqrt.approx.f32 %0, %1;" : "=f"(r) : "f"(x));
    return r;
}

// ---- packed f32x2 (FFMA2 path; PTX-only) ----
__device__ __forceinline__ u64 pack2(float lo, float hi) {
    u64 r; asm("mov.b64 %0, {%1, %2};" : "=l"(r) : "f"(lo), "f"(hi)); return r;
}
__device__ __forceinline__ void unpack2(float& lo, float& hi, u64 v) {
    asm("mov.b64 {%0, %1}, %2;" : "=f"(lo), "=f"(hi) : "l"(v));
}
__device__ __forceinline__ u64 mul2(u64 a, u64 b) {
    u64 r; asm("mul.rn.f32x2 %0, %1, %2;" : "=l"(r) : "l"(a), "l"(b)); return r;
}
__device__ __forceinline__ u64 add2(u64 a, u64 b) {
    u64 r; asm("add.rn.f32x2 %0, %1, %2;" : "=l"(r) : "l"(a), "l"(b)); return r;
}
__device__ __forceinline__ u64 fma2(u64 a, u64 b, u64 c) {
    u64 r; asm("fma.rn.f32x2 %0, %1, %2, %3;" : "=l"(r) : "l"(a), "l"(b), "l"(c)); return r;
}

// ---------------------------------------------------------------------------
// Kernel 1: fp32 row norms + fp16 convert. TWO rows per warp.
// grid = (QDIM+NDIM)/16 = 768 blocks of 256 threads
// ---------------------------------------------------------------------------
__global__ void __launch_bounds__(256)
prep_kernel(const float* __restrict__ query, const float* __restrict__ neigh) {
    int warp0 = (blockIdx.x * 256 + threadIdx.x) >> 5;   // 0..6143
    int l = threadIdx.x & 31;

#pragma unroll
    for (int k = 0; k < 2; ++k) {
        int row = warp0 * 2 + k;                          // 0..12287
        bool isQ = row < QDIM;
        int r = isQ ? row : row - QDIM;
        const float4* src = (const float4*)(isQ ? query + (size_t)r * DDIM
                                                : neigh + (size_t)r * DDIM);
        __half* dst = isQ ? g_A + (size_t)r * DDIM : g_B + (size_t)r * DDIM;

        float4 v0 = src[l * 2];
        float4 v1 = src[l * 2 + 1];

        float s = v0.x * v0.x + v0.y * v0.y + v0.z * v0.z + v0.w * v0.w
                + v1.x * v1.x + v1.y * v1.y + v1.z * v1.z + v1.w * v1.w;

        __half2 h0 = __floats2half2_rn(v0.x, v0.y);
        __half2 h1 = __floats2half2_rn(v0.z, v0.w);
        __half2 h2 = __floats2half2_rn(v1.x, v1.y);
        __half2 h3 = __floats2half2_rn(v1.z, v1.w);
        uint4 pk;
        pk.x = *(uint32_t*)&h0; pk.y = *(uint32_t*)&h1;
        pk.z = *(uint32_t*)&h2; pk.w = *(uint32_t*)&h3;
        ((uint4*)dst)[l] = pk;

#pragma unroll
        for (int off = 16; off > 0; off >>= 1)
            s += __shfl_xor_sync(0xffffffffu, s, off);
        if (l == 0) {
            if (isQ) g_q2[r] = s; else g_n2[r] = s;
        }
    }
}

// ---------------------------------------------------------------------------
// Kernel 2: HMMA fp16 GEMM (128x128 tile, K=256) + fused epilogue -> g_w
// stores e = exp(gumbel - dist). 8 warps 4(M)x2(N); 2 CTAs/SM
// ---------------------------------------------------------------------------
#define A_BYTES (BM * 128)                         // 16 KB
#define B_BYTES (BN * 128)                         // 16 KB
#define STAGE_BYTES (A_BYTES + B_BYTES)            // 32 KB
#define SMEM_DYN (STAGES * STAGE_BYTES)            // 96 KB

__device__ __forceinline__ void load_tile(uint32_t abuf, uint32_t bbuf,
                                          int kt, int qbase, int nbase,
                                          int tid) {
    const char* gA = (const char*)g_A + ((size_t)qbase * DDIM + (size_t)kt * BK) * 2;
    const char* gB = (const char*)g_B + ((size_t)nbase * DDIM + (size_t)kt * BK) * 2;
#pragma unroll
    for (int i = 0; i < 4; ++i) {
        int g = tid * 4 + i;
        int r = g >> 3, ku = g & 7;
        uint32_t so = (uint32_t)(r * 128 + ((ku ^ (r & 7)) << 4));
        cpasync16(abuf + so, gA + (size_t)r * (DDIM * 2) + (size_t)ku * 16);
        cpasync16(bbuf + so, gB + (size_t)r * (DDIM * 2) + (size_t)ku * 16);
    }
}

__global__ void __launch_bounds__(256, 2)
gemm_kernel(const float* __restrict__ gumbel) {
    extern __shared__ char smem_raw[];
    uint32_t sbase = smem_to_u32(smem_raw);

    int tid = threadIdx.x;
    int wid = tid >> 5;
    int l   = tid & 31;
    int warpm = wid & 3;          // 0..3 -> 32-row slab
    int warpn = wid >> 2;         // 0..1 -> 64-col slab

    int nbase = blockIdx.x * BN;
    int qbase = blockIdx.y * BM;

    uint32_t abuf[STAGES], bbuf[STAGES];
#pragma unroll
    for (int s = 0; s < STAGES; ++s) {
        abuf[s] = sbase + s * STAGE_BYTES;
        bbuf[s] = abuf[s] + A_BYTES;
    }

    load_tile(abuf[0], bbuf[0], 0, qbase, nbase, tid);
    cp_commit();
    load_tile(abuf[1], bbuf[1], 1, qbase, nbase, tid);
    cp_commit();

    float acc[2][8][4];
#pragma unroll
    for (int mt = 0; mt < 2; ++mt)
#pragma unroll
        for (int nt = 0; nt < 8; ++nt)
#pragma unroll
            for (int i = 0; i < 4; ++i) acc[mt][nt][i] = 0.f;

    int a_lr = (l & 15);
    int a_ku = (l >> 4);
    int b_lr = ((l >> 4) << 3) + (l & 7);
    int b_ku = ((l >> 3) & 1);

#pragma unroll
    for (int kt = 0; kt < NKT; ++kt) {
        const int s = kt % STAGES;
        if (kt < NKT - 1) cp_wait<1>();
        else              cp_wait<0>();
        __syncthreads();

        uint32_t aS = abuf[s], bS = bbuf[s];
#pragma unroll
        for (int ks = 0; ks < 4; ++ks) {
            int kb = ks * 2;
            uint32_t afr[2][4];
#pragma unroll
            for (int mt = 0; mt < 2; ++mt) {
                int r = warpm * 32 + mt * 16 + a_lr;
                uint32_t addr = aS + r * 128 + (((kb + a_ku) ^ (r & 7)) << 4);
                ldmatrix_x4(afr[mt], addr);
            }
            uint32_t bfr[4][4];
#pragma unroll
            for (int bt = 0; bt < 4; ++bt) {
                int r = warpn * 64 + bt * 16 + b_lr;
                uint32_t addr = bS + r * 128 + (((kb + b_ku) ^ (r & 7)) << 4);
                ldmatrix_x4(bfr[bt], addr);
            }
#pragma unroll
            for (int mt = 0; mt < 2; ++mt)
#pragma unroll
                for (int nt = 0; nt < 8; ++nt)
                    mma_fp16(acc[mt][nt], afr[mt], &bfr[nt >> 1][(nt & 1) * 2]);

            // Issue next-tile loads AFTER ks=0 compute: HMMA starts right at
            // the barrier; the 8-LDGSTS/thread issue burst overlaps ks=1..3.
            if (ks == 0 && kt + 2 < NKT) {
                load_tile(abuf[(kt + 2) % STAGES], bbuf[(kt + 2) % STAGES],
                          kt + 2, qbase, nbase, tid);
                cp_commit();
            }
        }
    }

    // Fused epilogue: e = exp(gumbel - sqrt.approx(max(q2 + n2 - 2*dot, 0)))
    {
        int row0 = qbase + warpm * 32 + (l >> 2);
        int colb = nbase + warpn * 64 + (l & 3) * 2;
#pragma unroll
        for (int mt = 0; mt < 2; ++mt) {
            int rA = row0 + mt * 16;
            int rB = rA + 8;
            float q2a = __ldg(&g_q2[rA]);
            float q2b = __ldg(&g_q2[rB]);
            const float2* gAraw = (const float2*)(gumbel + (size_t)rA * NDIM);
            const float2* gBraw = (const float2*)(gumbel + (size_t)rB * NDIM);
            float2* wA = (float2*)(g_w + (size_t)rA * NDIM);
            float2* wB = (float2*)(g_w + (size_t)rB * NDIM);
#pragma unroll
            for (int nt = 0; nt < 8; ++nt) {
                int col = colb + nt * 8;
                float n2a = __ldg(&g_n2[col]);
                float n2b = __ldg(&g_n2[col + 1]);
                float2 ga = __ldcs(&gAraw[col >> 1]);
                float2 gb = __ldcs(&gBraw[col >> 1]);
                float2 oa, ob;
                oa.x = __expf(ga.x - fsqrt_approx(fmaxf(fmaf(-2.f, acc[mt][nt][0], q2a + n2a), 0.f)));
                oa.y = __expf(ga.y - fsqrt_approx(fmaxf(fmaf(-2.f, acc[mt][nt][1], q2a + n2b), 0.f)));
                ob.x = __expf(gb.x - fsqrt_approx(fmaxf(fmaf(-2.f, acc[mt][nt][2], q2b + n2a), 0.f)));
                ob.y = __expf(gb.y - fsqrt_approx(fmaxf(fmaf(-2.f, acc[mt][nt][3], q2b + n2b), 0.f)));
                __stcs(&wA[col >> 1], oa);
                __stcs(&wB[col >> 1], ob);
            }
        }
    }
}

// ---------------------------------------------------------------------------
// Kernel 3: iterative relaxed top-k; one block (256 thr) per query row,
// 32 elems/thread, packed f32x2 math. Last-iteration e-update skipped (dead).
// ---------------------------------------------------------------------------
__global__ void __launch_bounds__(256)
iter_kernel(float* __restrict__ out) {
    __shared__ float sred[2][8];

    int t = threadIdx.x;
    int w = t >> 5, l = t & 31;
    const float4* erow = (const float4*)(g_w + (size_t)blockIdx.x * NDIM);
    float4* orow = (float4*)(out + (size_t)blockIdx.x * NDIM);

    u64 e2[16], kh2[16];
#pragma unroll
    for (int i = 0; i < 8; ++i) {
        float4 v = __ldcs(&erow[i * 256 + t]);
        e2[i * 2 + 0] = pack2(v.x, v.y);
        e2[i * 2 + 1] = pack2(v.z, v.w);
    }
    const u64 zero2 = pack2(0.f, 0.f);
    const u64 none2 = pack2(-1.f, -1.f);
#pragma unroll
    for (int j = 0; j < 16; ++j) kh2[j] = zero2;

#pragma unroll
    for (int it = 0; it < NITER; ++it) {
        int buf = it & 1;
        u64 sa = e2[0], sb = e2[1], sc = e2[2], sd = e2[3];
#pragma unroll
        for (int j = 4; j < 16; j += 4) {
            sa = add2(sa, e2[j]);     sb = add2(sb, e2[j + 1]);
            sc = add2(sc, e2[j + 2]); sd = add2(sd, e2[j + 3]);
        }
        u64 st2 = add2(add2(sa, sb), add2(sc, sd));
        float slo, shi; unpack2(slo, shi, st2);
        float s = slo + shi;
#pragma unroll
        for (int o = 16; o > 0; o >>= 1)
            s += __shfl_xor_sync(0xffffffffu, s, o);
        if (l == 0) sred[buf][w] = s;
        __syncthreads();
        float tot = sred[buf][0];
#pragma unroll
        for (int j = 1; j < 8; ++j) tot += sred[buf][j];
        float ninv = -__fdividef(1.0f, tot);
        u64 ninv2 = pack2(ninv, ninv);
        if (it < NITER - 1) {
#pragma unroll
            for (int j = 0; j < 16; ++j) {
                u64 np = mul2(e2[j], ninv2);        // np = -p
                kh2[j] = fma2(np, none2, kh2[j]);   // kh += p
                e2[j]  = fma2(np, e2[j], e2[j]);    // e *= (1 - p)
            }
        } else {
#pragma unroll
            for (int j = 0; j < 16; ++j) {
                u64 np = mul2(e2[j], ninv2);        // np = -p
                kh2[j] = fma2(np, none2, kh2[j]);   // kh += p (e update dead)
            }
        }
    }

#pragma unroll
    for (int i = 0; i < 8; ++i) {
        float4 o4;
        unpack2(o4.x, o4.y, kh2[i * 2 + 0]);
        unpack2(o4.z, o4.w, kh2[i * 2 + 1]);
        __stcs(&orow[i * 256 + t], o4);
    }
}

// ---------------------------------------------------------------------------
// Launch (serial; overlap impossible: GEMM occupies the full register file)
// ---------------------------------------------------------------------------
extern "C" void kernel_launch(void* const* d_in, const int* in_sizes, int n_in,
                              void* d_out, int out_size) {
    const float* query  = (const float*)d_in[0];   // [4096, 256]
    const float* neigh  = (const float*)d_in[1];   // [1, 8192, 256]
    const float* gumbel = (const float*)d_in[2];   // [4096, 8192]
    float* out = (float*)d_out;                    // [4096, 8192]

    prep_kernel<<<(QDIM + NDIM) / 16, 256>>>(query, neigh);

    cudaFuncSetAttribute(gemm_kernel,
                         cudaFuncAttributeMaxDynamicSharedMemorySize, SMEM_DYN);
    dim3 grid(NDIM / BN, QDIM / BM);
    gemm_kernel<<<grid, 256, SMEM_DYN>>>(gumbel);

    iter_kernel<<<QDIM, 256>>>(out);
}